// round 15
// baseline (speedup 1.0000x reference)
#include <cuda_runtime.h>
#include <math.h>

#define HS   14
#define SEQ  197
#define FULL 0xFFFFFFFFu

// Two tasks per warp: task A = lanes 0-15, task B = lanes 16-31.
// sub-lane 0..13 owns a grid row; sub 14,15 hold all-0xFF pad rows.
// Labels are padded addresses: row*16 + col (<=221), order-isomorphic to
// flat index, so min-root identity matches the reference segments.
__global__ __launch_bounds__(32) void blob_loss_kernel(
    const float* __restrict__ dot_qk,
    float* __restrict__ out,
    float inv_n)
{
    // Per buffer, per task: [16B guard][rows 0..15 = 256B][16B guard] = 288B.
    // Guards stay 0xFF forever -> branch-free row r-1 / r+1 vector loads.
    __shared__ __align__(16) unsigned char SLAB[2][576];
    __shared__ float PU[2][224];

    const int lane = threadIdx.x;
    const int sub  = lane & 15;
    const int half = lane >> 4;
    const int task = blockIdx.x * 2 + half;
    const int tbase = half * 288 + 16;          // start of rows 0..15

    const bool   rowok = (sub < HS);
    const float* myrow = dot_qk + (size_t)task * (SEQ * SEQ) + 1 + sub * HS;

    // init SLAB (both buffers, 1152B) to 0xFF and PU to 0
    #pragma unroll
    for (int i = lane; i < 72; i += 32)
        ((uint4*)SLAB)[i] = make_uint4(FULL, FULL, FULL, FULL);
    #pragma unroll
    for (int i = lane; i < 448; i += 32) PU[0][i] = 0.f;

    // ---- load 14 register floats per row-lane; mean per 16-lane half
    float x[HS];
    float rs = 0.f;
    #pragma unroll
    for (int c = 0; c < HS; c++) {
        x[c] = rowok ? myrow[c] : 0.f;
        rs += x[c];
    }
    float s = rs;
    #pragma unroll
    for (int o = 8; o; o >>= 1) s += __shfl_xor_sync(FULL, s, o);
    const float m = s * (1.0f / 196.0f);

    // ---- mask + B (xv recomputed in epilogue to save registers)
    unsigned mk = 0;
    float b = 0.f;
    #pragma unroll
    for (int c = 0; c < HS; c++) {
        if (rowok && x[c] > m) { mk |= (1u << c); b += (x[c] - m) + 1e-9f; }
    }
    float B = b;
    #pragma unroll
    for (int o = 8; o; o >>= 1) B += __shfl_xor_sync(FULL, B, o);

    // ---- initial labels = horizontal run-start address (label <= own address)
    const unsigned abase = (unsigned)(sub << 4);
    unsigned w0, w1, w2, w3;
    {
        unsigned ww[4];
        unsigned start = 0;
        #pragma unroll
        for (int i = 0; i < 4; i++) {
            unsigned v = 0;
            #pragma unroll
            for (int j = 0; j < 4; j++) {
                int c = 4 * i + j;
                unsigned byte = 0xFFu;
                if (c < HS && ((mk >> c) & 1u)) {
                    if (c == 0 || !((mk >> (c - 1)) & 1u)) start = (unsigned)c;
                    byte = abase + start;
                }
                v |= byte << (8 * j);
            }
            ww[i] = v;
        }
        w0 = ww[0]; w1 = ww[1]; w2 = ww[2]; w3 = ww[3];
    }
    const unsigned nn0 = __vcmpeq4(w0, FULL);   // 0xFF bytes = background/pad
    const unsigned nn1 = __vcmpeq4(w1, FULL);
    const unsigned nn2 = __vcmpeq4(w2, FULL);
    const unsigned nn3 = __vcmpeq4(w3, FULL);
    __syncwarp();   // SLAB init visible before first iteration's reads

    // ---- CC loop: horizontal min (regs) -> mirror h -> vertical min via
    //      LDS of rows r±1 (replaces 16 SHFLs) -> pointer jump (byte gather).
    //      h keeps background leaks: they carry exactly the diagonal terms.
    int bi = 0;
    for (int it = 0; it < 64; it++) {
        unsigned h0, h1, h2, h3;
        {
            unsigned sr0 = __funnelshift_r(w0, w1, 8);
            unsigned sr1 = __funnelshift_r(w1, w2, 8);
            unsigned sr2 = __funnelshift_r(w2, w3, 8);
            unsigned sr3 = __funnelshift_r(w3, FULL, 8);
            unsigned sl0 = __funnelshift_l(FULL, w0, 8);
            unsigned sl1 = __funnelshift_l(w0, w1, 8);
            unsigned sl2 = __funnelshift_l(w1, w2, 8);
            unsigned sl3 = __funnelshift_l(w2, w3, 8);
            h0 = __vminu4(w0, __vminu4(sr0, sl0));
            h1 = __vminu4(w1, __vminu4(sr1, sl1));
            h2 = __vminu4(w2, __vminu4(sr2, sl2));
            h3 = __vminu4(w3, __vminu4(sr3, sl3));
        }

        // mirror h (pad lanes mirror 0xFF rows; guards never written)
        *(uint4*)&SLAB[bi][tbase + (sub << 4)] = make_uint4(h0, h1, h2, h3);
        __syncwarp();
        const unsigned char* Sb = &SLAB[bi][tbase];

        // vertical 3-min from mirrored h rows (sub-1 / sub+1 hit guards at edges)
        uint4 up = *(const uint4*)(Sb + ((sub - 1) << 4));
        uint4 dn = *(const uint4*)(Sb + ((sub + 1) << 4));
        unsigned t0 = __vminu4(h0, __vminu4(up.x, dn.x)) | nn0;
        unsigned t1 = __vminu4(h1, __vminu4(up.y, dn.y)) | nn1;
        unsigned t2 = __vminu4(h2, __vminu4(up.z, dn.z)) | nn2;
        unsigned t3 = __vminu4(h3, __vminu4(up.w, dn.w)) | nn3;

        // pointer jump through the same h-table: g = Sb[t] (monotone, in-component;
        // background bytes 0xFF gather Sb[255] which lane 15 keeps at 0xFF)
        unsigned a0  = Sb[t0 & 0xFFu],         a1  = Sb[(t0 >> 8) & 0xFFu];
        unsigned a2  = Sb[(t0 >> 16) & 0xFFu], a3  = Sb[t0 >> 24];
        unsigned a4  = Sb[t1 & 0xFFu],         a5  = Sb[(t1 >> 8) & 0xFFu];
        unsigned a6  = Sb[(t1 >> 16) & 0xFFu], a7  = Sb[t1 >> 24];
        unsigned a8  = Sb[t2 & 0xFFu],         a9  = Sb[(t2 >> 8) & 0xFFu];
        unsigned a10 = Sb[(t2 >> 16) & 0xFFu], a11 = Sb[t2 >> 24];
        unsigned a12 = Sb[t3 & 0xFFu],         a13 = Sb[(t3 >> 8) & 0xFFu];
        unsigned g0 = a0  | (a1  << 8) | (a2  << 16) | (a3  << 24);
        unsigned g1 = a4  | (a5  << 8) | (a6  << 16) | (a7  << 24);
        unsigned g2 = a8  | (a9  << 8) | (a10 << 16) | (a11 << 24);
        unsigned g3 = (a12 | (a13 << 8) | 0xFFFF0000u) | nn3;

        unsigned ch = (g0 ^ w0) | (g1 ^ w1) | (g2 ^ w2) | (g3 ^ w3);
        w0 = g0; w1 = g1; w2 = g2; w3 = g3;
        bi ^= 1;
        if (!__any_sync(FULL, ch != 0u)) break;
    }

    // ---- per-component sums (task-local padded addresses)
    __syncwarp();
    float* PUt = PU[half];
    if (rowok) {
        #pragma unroll
        for (int c = 0; c < HS; c++) {
            if ((mk >> c) & 1u) {
                unsigned lb;
                if      (c < 4)  lb = (w0 >> (8 * c))        & 0xFFu;
                else if (c < 8)  lb = (w1 >> (8 * (c - 4)))  & 0xFFu;
                else if (c < 12) lb = (w2 >> (8 * (c - 8)))  & 0xFFu;
                else             lb = (w3 >> (8 * (c - 12))) & 0xFFu;
                atomicAdd(&PUt[lb], (x[c] - m) + 1e-9f);
            }
        }
    }
    __syncwarp();

    // ---- entropy at roots (label == own padded address), reduce per half
    float h = 0.f;
    const float invB = 1.0f / B;
    if (rowok) {
        #pragma unroll
        for (int c = 0; c < HS; c++) {
            if ((mk >> c) & 1u) {
                unsigned lb;
                if      (c < 4)  lb = (w0 >> (8 * c))        & 0xFFu;
                else if (c < 8)  lb = (w1 >> (8 * (c - 4)))  & 0xFFu;
                else if (c < 12) lb = (w2 >> (8 * (c - 8)))  & 0xFFu;
                else             lb = (w3 >> (8 * (c - 12))) & 0xFFu;
                if (lb == abase + c) {
                    float pn = PUt[lb] * invB;
                    h -= pn * __logf(pn);
                }
            }
        }
    }
    #pragma unroll
    for (int o = 8; o; o >>= 1) h += __shfl_xor_sync(FULL, h, o);
    if (sub == 0) atomicAdd(out, h * inv_n);
}

extern "C" void kernel_launch(void* const* d_in, const int* in_sizes, int n_in,
                              void* d_out, int out_size)
{
    const float* dq = (const float*)d_in[0];
    float* out = (float*)d_out;
    const int n = in_sizes[0] / (SEQ * SEQ);   // 128*12 = 1536 (even)

    cudaMemsetAsync(out, 0, sizeof(float));
    blob_loss_kernel<<<n / 2, 32>>>(dq, out, 1.0f / (float)n);
}

// round 17
// speedup vs baseline: 1.0016x; 1.0016x over previous
#include <cuda_runtime.h>
#include <math.h>

#define HS   14
#define SEQ  197
#define FULL 0xFFFFFFFFu

// Two tasks per warp: task A = lanes 0-15, task B = lanes 16-31.
// sub-lane 0..13 owns a grid row; sub 14,15 hold all-0xFF pad rows.
// Labels are padded addresses: row*16 + col (<=221), order-isomorphic to
// flat index, so min-root identity matches the reference segments.
__global__ __launch_bounds__(32) void blob_loss_kernel(
    const float* __restrict__ dot_qk,
    float* __restrict__ out,
    float inv_n)
{
    __shared__ __align__(16) unsigned char SLAB[2][512];  // 256B/task; slot 255 = 0xFF
    __shared__ float PU[2][224];

    const int lane = threadIdx.x;
    const int sub  = lane & 15;
    const int half = lane >> 4;
    const int task = blockIdx.x * 2 + half;
    const unsigned tofs = (unsigned)(half << 8);

    const bool   rowok = (sub < HS);
    const float* myrow = dot_qk + (size_t)task * (SEQ * SEQ) + 1 + sub * HS;

    ((uint4*)SLAB[0])[lane] = make_uint4(FULL, FULL, FULL, FULL);
    ((uint4*)SLAB[1])[lane] = make_uint4(FULL, FULL, FULL, FULL);
    #pragma unroll
    for (int i = lane; i < 448; i += 32) PU[0][i] = 0.f;

    // ---- load 14 register floats per row-lane; mean per 16-lane half
    float x[HS];
    float rs = 0.f;
    #pragma unroll
    for (int c = 0; c < HS; c++) {
        x[c] = rowok ? myrow[c] : 0.f;
        rs += x[c];
    }
    float s = rs;
    #pragma unroll
    for (int o = 8; o; o >>= 1) s += __shfl_xor_sync(FULL, s, o);
    const float m = s * (1.0f / 196.0f);

    // ---- mask + B
    unsigned mk = 0;
    float b = 0.f;
    #pragma unroll
    for (int c = 0; c < HS; c++) {
        if (rowok && x[c] > m) { mk |= (1u << c); b += (x[c] - m) + 1e-9f; }
    }
    float B = b;
    #pragma unroll
    for (int o = 8; o; o >>= 1) B += __shfl_xor_sync(FULL, B, o);

    // ---- initial labels = horizontal run-start address (free row closure)
    const unsigned abase = (unsigned)(sub << 4);
    unsigned w0, w1, w2, w3;
    {
        unsigned ww[4];
        unsigned start = 0;
        #pragma unroll
        for (int i = 0; i < 4; i++) {
            unsigned v = 0;
            #pragma unroll
            for (int j = 0; j < 4; j++) {
                int c = 4 * i + j;
                unsigned byte = 0xFFu;
                if (c < HS && ((mk >> c) & 1u)) {
                    if (c == 0 || !((mk >> (c - 1)) & 1u)) start = (unsigned)c;
                    byte = abase + start;
                }
                v |= byte << (8 * j);
            }
            ww[i] = v;
        }
        w0 = ww[0]; w1 = ww[1]; w2 = ww[2]; w3 = ww[3];
    }
    const unsigned nn0 = __vcmpeq4(w0, FULL);
    const unsigned nn1 = __vcmpeq4(w1, FULL);
    const unsigned nn2 = __vcmpeq4(w2, FULL);
    const unsigned nn3 = __vcmpeq4(w3, FULL);
    __syncwarp();

    // ---- CC: one 8-neighbor byte-min (registers) + TRIPLE pointer jump through
    //      the mirrored h-table (aggressive path compression -> O(log) rounds).
    //      Monotone & component-internal; vote on exact minstep fixpoint.
    //      Cap 196 is sound: each iteration contains one full masked min-step,
    //      and 196 min-steps alone reach the fixpoint (jumps only accelerate).
    int bi = 0;
    for (int it = 0; it < 196; it++) {
        unsigned h0, h1, h2, h3;
        {
            unsigned sr0 = __funnelshift_r(w0, w1, 8);
            unsigned sr1 = __funnelshift_r(w1, w2, 8);
            unsigned sr2 = __funnelshift_r(w2, w3, 8);
            unsigned sr3 = __funnelshift_r(w3, FULL, 8);
            unsigned sl0 = __funnelshift_l(FULL, w0, 8);
            unsigned sl1 = __funnelshift_l(w0, w1, 8);
            unsigned sl2 = __funnelshift_l(w1, w2, 8);
            unsigned sl3 = __funnelshift_l(w2, w3, 8);
            unsigned a0 = __vminu4(w0, __vminu4(sr0, sl0));
            unsigned a1 = __vminu4(w1, __vminu4(sr1, sl1));
            unsigned a2 = __vminu4(w2, __vminu4(sr2, sl2));
            unsigned a3 = __vminu4(w3, __vminu4(sr3, sl3));
            unsigned u0 = __shfl_up_sync(FULL, a0, 1), d0 = __shfl_down_sync(FULL, a0, 1);
            unsigned u1 = __shfl_up_sync(FULL, a1, 1), d1 = __shfl_down_sync(FULL, a1, 1);
            unsigned u2 = __shfl_up_sync(FULL, a2, 1), d2 = __shfl_down_sync(FULL, a2, 1);
            unsigned u3 = __shfl_up_sync(FULL, a3, 1), d3 = __shfl_down_sync(FULL, a3, 1);
            h0 = __vminu4(a0, __vminu4(u0, d0)) | nn0;
            h1 = __vminu4(a1, __vminu4(u1, d1)) | nn1;
            h2 = __vminu4(a2, __vminu4(u2, d2)) | nn2;
            h3 = __vminu4(a3, __vminu4(u3, d3)) | nn3;
        }

        // mirror h (pad lanes write 0xFF rows; slot 255 stays 0xFF)
        *(uint4*)&SLAB[bi][tofs + abase] = make_uint4(h0, h1, h2, h3);
        __syncwarp();
        const unsigned char* S = &SLAB[bi][tofs];

        // triple jump: g = S[S[S[h]]]
        unsigned a0  = S[h0 & 0xFFu],         a1  = S[(h0 >> 8) & 0xFFu];
        unsigned a2  = S[(h0 >> 16) & 0xFFu], a3  = S[h0 >> 24];
        unsigned a4  = S[h1 & 0xFFu],         a5  = S[(h1 >> 8) & 0xFFu];
        unsigned a6  = S[(h1 >> 16) & 0xFFu], a7  = S[h1 >> 24];
        unsigned a8  = S[h2 & 0xFFu],         a9  = S[(h2 >> 8) & 0xFFu];
        unsigned a10 = S[(h2 >> 16) & 0xFFu], a11 = S[h2 >> 24];
        unsigned a12 = S[h3 & 0xFFu],         a13 = S[(h3 >> 8) & 0xFFu];
        a0  = S[a0];  a1  = S[a1];  a2  = S[a2];  a3  = S[a3];
        a4  = S[a4];  a5  = S[a5];  a6  = S[a6];  a7  = S[a7];
        a8  = S[a8];  a9  = S[a9];  a10 = S[a10]; a11 = S[a11];
        a12 = S[a12]; a13 = S[a13];
        a0  = S[a0];  a1  = S[a1];  a2  = S[a2];  a3  = S[a3];
        a4  = S[a4];  a5  = S[a5];  a6  = S[a6];  a7  = S[a7];
        a8  = S[a8];  a9  = S[a9];  a10 = S[a10]; a11 = S[a11];
        a12 = S[a12]; a13 = S[a13];

        unsigned g0 = a0  | (a1  << 8) | (a2  << 16) | (a3  << 24);
        unsigned g1 = a4  | (a5  << 8) | (a6  << 16) | (a7  << 24);
        unsigned g2 = a8  | (a9  << 8) | (a10 << 16) | (a11 << 24);
        unsigned g3 = a12 | (a13 << 8) | 0xFFFF0000u;

        unsigned ch = (g0 ^ w0) | (g1 ^ w1) | (g2 ^ w2) | (g3 ^ w3);
        w0 = g0; w1 = g1; w2 = g2; w3 = g3;
        bi ^= 1;
        if (!__any_sync(FULL, ch != 0u)) break;
    }

    // ---- per-component sums (task-local padded addresses)
    __syncwarp();
    float* PUt = PU[half];
    if (rowok) {
        #pragma unroll
        for (int c = 0; c < HS; c++) {
            if ((mk >> c) & 1u) {
                unsigned lb;
                if      (c < 4)  lb = (w0 >> (8 * c))        & 0xFFu;
                else if (c < 8)  lb = (w1 >> (8 * (c - 4)))  & 0xFFu;
                else if (c < 12) lb = (w2 >> (8 * (c - 8)))  & 0xFFu;
                else             lb = (w3 >> (8 * (c - 12))) & 0xFFu;
                atomicAdd(&PUt[lb], (x[c] - m) + 1e-9f);
            }
        }
    }
    __syncwarp();

    // ---- entropy at roots (label == own padded address), reduce per half
    float h = 0.f;
    const float invB = 1.0f / B;
    if (rowok) {
        #pragma unroll
        for (int c = 0; c < HS; c++) {
            if ((mk >> c) & 1u) {
                unsigned lb;
                if      (c < 4)  lb = (w0 >> (8 * c))        & 0xFFu;
                else if (c < 8)  lb = (w1 >> (8 * (c - 4)))  & 0xFFu;
                else if (c < 12) lb = (w2 >> (8 * (c - 8)))  & 0xFFu;
                else             lb = (w3 >> (8 * (c - 12))) & 0xFFu;
                if (lb == abase + c) {
                    float pn = PUt[lb] * invB;
                    h -= pn * __logf(pn);
                }
            }
        }
    }
    #pragma unroll
    for (int o = 8; o; o >>= 1) h += __shfl_xor_sync(FULL, h, o);
    if (sub == 0) atomicAdd(out, h * inv_n);
}

extern "C" void kernel_launch(void* const* d_in, const int* in_sizes, int n_in,
                              void* d_out, int out_size)
{
    const float* dq = (const float*)d_in[0];
    float* out = (float*)d_out;
    const int n = in_sizes[0] / (SEQ * SEQ);   // 128*12 = 1536 (even)

    cudaMemsetAsync(out, 0, sizeof(float));
    blob_loss_kernel<<<n / 2, 32>>>(dq, out, 1.0f / (float)n);
}